// round 1
// baseline (speedup 1.0000x reference)
#include <cuda_runtime.h>

// NerfModel: masked voxel gather + SH(deg 2) eval.
// Inputs (metadata order): x [M,3] f32, d [M,3] f32, voxel_grid [200,200,200,28] f32.
// Output: color [M,3] then sigma [M], concatenated (out_size = 4*M floats).

#define SCALE 1.5f
#define GRID_N 200

__global__ __launch_bounds__(256) void nerf_kernel(
    const float* __restrict__ x,
    const float* __restrict__ d,
    const float* __restrict__ vg,
    float* __restrict__ out,
    int M)
{
    int i = blockIdx.x * blockDim.x + threadIdx.x;
    if (i >= M) return;

    float x0 = x[3 * i + 0];
    float x1 = x[3 * i + 1];
    float x2 = x[3 * i + 2];

    bool mask = (fabsf(x0) < SCALE) & (fabsf(x1) < SCALE) & (fabsf(x2) < SCALE);

    float* color = out + 3 * (size_t)i;
    float* sigma = out + 3 * (size_t)M + i;

    if (!mask) {
        color[0] = 0.0f;
        color[1] = 0.0f;
        color[2] = 0.0f;
        *sigma = 0.0f;
        return;
    }

    // idx = clip(int(x / (2*SCALE/N) + N/2), 0, N-1); 2*1.5/200 = 0.015
    const float step = 2.0f * SCALE / (float)GRID_N;   // 0.015f
    int i0 = (int)(x0 / step + (float)GRID_N * 0.5f);
    int i1 = (int)(x1 / step + (float)GRID_N * 0.5f);
    int i2 = (int)(x2 / step + (float)GRID_N * 0.5f);
    i0 = min(max(i0, 0), GRID_N - 1);
    i1 = min(max(i1, 0), GRID_N - 1);
    i2 = min(max(i2, 0), GRID_N - 1);

    int voxel = (i0 * GRID_N + i1) * GRID_N + i2;      // < 8e6, fits int
    const float4* p = (const float4*)(vg + (size_t)voxel * 28); // 112B, 16B-aligned

    float4 t0 = __ldg(p + 0);
    float4 t1 = __ldg(p + 1);
    float4 t2 = __ldg(p + 2);
    float4 t3 = __ldg(p + 3);
    float4 t4 = __ldg(p + 4);
    float4 t5 = __ldg(p + 5);
    float4 t6 = __ldg(p + 6);

    float t[28] = {
        t0.x, t0.y, t0.z, t0.w,
        t1.x, t1.y, t1.z, t1.w,
        t2.x, t2.y, t2.z, t2.w,
        t3.x, t3.y, t3.z, t3.w,
        t4.x, t4.y, t4.z, t4.w,
        t5.x, t5.y, t5.z, t5.w,
        t6.x, t6.y, t6.z, t6.w,
    };

    *sigma = fmaxf(t[0], 0.0f);

    float dx = d[3 * i + 0];
    float dy = d[3 * i + 1];
    float dz = d[3 * i + 2];

    // SH basis (degree 2, 9 coefficients)
    float b[9];
    b[0] = 0.282095f;
    b[1] = -0.488603f * dy;
    b[2] = 0.488603f * dz;
    b[3] = -0.488603f * dx;
    b[4] = 1.092548f * dx * dy;
    b[5] = -1.092548f * dy * dz;
    b[6] = 0.315392f * (2.0f * dz * dz - dx * dx - dy * dy);
    b[7] = -1.092548f * dx * dz;
    b[8] = 0.546274f * (dx * dx - dy * dy);

    #pragma unroll
    for (int c = 0; c < 3; c++) {
        const float* k = t + 1 + 9 * c;
        float acc = 0.0f;
        #pragma unroll
        for (int j = 0; j < 9; j++)
            acc = fmaf(b[j], k[j], acc);
        color[c] = acc;
    }
}

extern "C" void kernel_launch(void* const* d_in, const int* in_sizes, int n_in,
                              void* d_out, int out_size) {
    const float* x  = (const float*)d_in[0];
    const float* d  = (const float*)d_in[1];
    const float* vg = (const float*)d_in[2];
    float* out = (float*)d_out;

    int M = in_sizes[0] / 3;   // x is [M,3]
    int threads = 256;
    int blocks = (M + threads - 1) / threads;
    nerf_kernel<<<blocks, threads>>>(x, d, vg, out, M);
}

// round 4
// speedup vs baseline: 1.1185x; 1.1185x over previous
#include <cuda_runtime.h>

// NerfModel: masked voxel gather + SH(deg 2) eval.
// Inputs: x [M,3] f32, d [M,3] f32, voxel_grid [200,200,200,28] f32.
// Output: color [M,3] then sigma [M] (out_size = 4*M floats).
//
// R2: cooperative smem gather. Per block of 256 rays:
//  - phase 1: load x+d concurrently, compute mask + voxel base, zero outputs
//             for masked-out rays, publish base to smem.
//  - phase 2: all 256 threads cooperatively issue the 7*(#masked) float4
//             gathers into smem (independent burst -> high MLP).
//  - phase 3: ray owner reads 28 floats from smem (stride 112B, 16B aligned,
//             bank-conflict-free in 8-lane phases) and evaluates SH.

#define SCALE 1.5f
#define GRID_N 200
#define BLK 256

__global__ __launch_bounds__(BLK, 8) void nerf_kernel(
    const float* __restrict__ x,
    const float* __restrict__ d,
    const float* __restrict__ vg,
    float* __restrict__ out,
    int M)
{
    __shared__ float srec[BLK * 28];   // 28 KB
    __shared__ int   sbase[BLK];       // float4 index of record, or -1

    const int tid = threadIdx.x;
    const int ray = blockIdx.x * BLK + tid;

    float dx = 0.0f, dy = 0.0f, dz = 0.0f;
    int base = -1;

    if (ray < M) {
        // x and d loads issued together (independent)
        float x0 = x[3 * ray + 0];
        float x1 = x[3 * ray + 1];
        float x2 = x[3 * ray + 2];
        dx = d[3 * ray + 0];
        dy = d[3 * ray + 1];
        dz = d[3 * ray + 2];

        bool mask = (fabsf(x0) < SCALE) & (fabsf(x1) < SCALE) & (fabsf(x2) < SCALE);

        if (mask) {
            const float step = 2.0f * SCALE / (float)GRID_N;   // 0.015f
            int i0 = (int)(x0 / step + (float)GRID_N * 0.5f);
            int i1 = (int)(x1 / step + (float)GRID_N * 0.5f);
            int i2 = (int)(x2 / step + (float)GRID_N * 0.5f);
            i0 = min(max(i0, 0), GRID_N - 1);
            i1 = min(max(i1, 0), GRID_N - 1);
            i2 = min(max(i2, 0), GRID_N - 1);
            base = ((i0 * GRID_N + i1) * GRID_N + i2) * 7;     // float4 units
        } else {
            float* color = out + 3 * (size_t)ray;
            color[0] = 0.0f;
            color[1] = 0.0f;
            color[2] = 0.0f;
            out[3 * (size_t)M + ray] = 0.0f;
        }
    }
    sbase[tid] = base;
    __syncthreads();

    // Cooperative gather: 7 float4 per masked ray, flat independent burst.
    const float4* vg4 = (const float4*)vg;
    #pragma unroll
    for (int k = 0; k < 7; k++) {
        int s = tid + k * BLK;          // 0 .. 1791
        int r = s / 7;
        int q = s - r * 7;
        int b = sbase[r];
        if (b >= 0) {
            float4 v = __ldg(vg4 + b + q);
            *(float4*)&srec[r * 28 + q * 4] = v;
        }
    }
    __syncthreads();

    if (base >= 0) {
        const float* t = &srec[tid * 28];

        out[3 * (size_t)M + ray] = fmaxf(t[0], 0.0f);

        // SH basis (degree 2, 9 coefficients)
        float b0 = 0.282095f;
        float b1 = -0.488603f * dy;
        float b2 = 0.488603f * dz;
        float b3 = -0.488603f * dx;
        float b4 = 1.092548f * dx * dy;
        float b5 = -1.092548f * dy * dz;
        float b6 = 0.315392f * (2.0f * dz * dz - dx * dx - dy * dy);
        float b7 = -1.092548f * dx * dz;
        float b8 = 0.546274f * (dx * dx - dy * dy);

        float* color = out + 3 * (size_t)ray;
        #pragma unroll
        for (int c = 0; c < 3; c++) {
            const float* k = t + 1 + 9 * c;
            float acc;
            acc = b0 * k[0];
            acc = fmaf(b1, k[1], acc);
            acc = fmaf(b2, k[2], acc);
            acc = fmaf(b3, k[3], acc);
            acc = fmaf(b4, k[4], acc);
            acc = fmaf(b5, k[5], acc);
            acc = fmaf(b6, k[6], acc);
            acc = fmaf(b7, k[7], acc);
            acc = fmaf(b8, k[8], acc);
            color[c] = acc;
        }
    }
}

extern "C" void kernel_launch(void* const* d_in, const int* in_sizes, int n_in,
                              void* d_out, int out_size) {
    const float* x  = (const float*)d_in[0];
    const float* d  = (const float*)d_in[1];
    const float* vg = (const float*)d_in[2];
    float* out = (float*)d_out;

    int M = in_sizes[0] / 3;
    int blocks = (M + BLK - 1) / BLK;
    nerf_kernel<<<blocks, BLK>>>(x, d, vg, out, M);
}

// round 5
// speedup vs baseline: 1.5359x; 1.3732x over previous
#include <cuda_runtime.h>
#include <cstdint>

// NerfModel: masked voxel gather + SH(deg 2) eval.
// Inputs: x [M,3] f32, d [M,3] f32, voxel_grid [200,200,200,28] f32.
// Output: color [M,3] then sigma [M] (out_size = 4*M floats).
//
// R3: persistent blocks, double-buffered cp.async gather pipeline.
//   - 128-ray tiles, grid-stride. Two smem buffers.
//   - iter i: PREP(i+1) [x load, mask, base, predicated d load],
//             sync, issue cp.async gathers(i+1), commit,
//             wait_group 1 (tile i complete), sync, COMPUTE(i).
//   - Gather requests stay in flight across compute/prep -> continuous DRAM
//     supply instead of phase-aligned bursts.

#define SCALE 1.5f
#define GRID_N 200
#define BLK 128
#define TILE 128

__device__ __forceinline__ int prep_tile(
    const float* __restrict__ x, const float* __restrict__ d,
    int M, int tile, int tid, int* sbase_buf,
    float& dx, float& dy, float& dz)
{
    int ray = tile * TILE + tid;
    int base = -1;
    dx = dy = dz = 0.0f;
    if (ray < M) {
        float x0 = __ldg(&x[3 * ray + 0]);
        float x1 = __ldg(&x[3 * ray + 1]);
        float x2 = __ldg(&x[3 * ray + 2]);
        bool mask = (fabsf(x0) < SCALE) & (fabsf(x1) < SCALE) & (fabsf(x2) < SCALE);
        if (mask) {
            const float step = 2.0f * SCALE / (float)GRID_N;   // 0.015f
            int i0 = (int)(x0 / step + (float)GRID_N * 0.5f);
            int i1 = (int)(x1 / step + (float)GRID_N * 0.5f);
            int i2 = (int)(x2 / step + (float)GRID_N * 0.5f);
            i0 = min(max(i0, 0), GRID_N - 1);
            i1 = min(max(i1, 0), GRID_N - 1);
            i2 = min(max(i2, 0), GRID_N - 1);
            base = ((i0 * GRID_N + i1) * GRID_N + i2) * 7;     // float4 units
            dx = __ldg(&d[3 * ray + 0]);
            dy = __ldg(&d[3 * ray + 1]);
            dz = __ldg(&d[3 * ray + 2]);
        }
    }
    sbase_buf[tid] = base;
    return base;
}

__device__ __forceinline__ void gather_tile(
    const float* __restrict__ vg, const int* sbase_buf,
    float* srec_buf, int tid)
{
    // TILE*7 = 896 slots, BLK=128 threads -> 7 iterations.
    #pragma unroll
    for (int k = 0; k < 7; k++) {
        int s = tid + k * BLK;
        int r = s / 7;
        int q = s - r * 7;
        int b = sbase_buf[r];
        if (b >= 0) {
            const char* src = (const char*)vg + (((size_t)(b + q)) << 4);
            uint32_t dst = (uint32_t)__cvta_generic_to_shared(srec_buf + r * 28 + q * 4);
            asm volatile("cp.async.cg.shared.global [%0], [%1], 16;\n"
                         :: "r"(dst), "l"(src) : "memory");
        }
    }
}

__global__ __launch_bounds__(BLK) void nerf_kernel(
    const float* __restrict__ x,
    const float* __restrict__ d,
    const float* __restrict__ vg,
    float* __restrict__ out,
    int M, int ntiles)
{
    __shared__ float srec[2][TILE * 28];   // 28 KB
    __shared__ int   sbase[2][TILE];

    const int tid = threadIdx.x;
    const int stride = gridDim.x;

    int tile0 = blockIdx.x;
    if (tile0 >= ntiles) return;

    // Prolog: tile0 into buffer 0.
    float d0x, d0y, d0z;
    int base0 = prep_tile(x, d, M, tile0, tid, sbase[0], d0x, d0y, d0z);
    __syncthreads();
    gather_tile(vg, sbase[0], srec[0], tid);
    asm volatile("cp.async.commit_group;\n" ::: "memory");

    int i = tile0;
    int buf = 0;

    while (i < ntiles) {
        int nexti = i + stride;
        int nbuf = buf ^ 1;

        float d1x = 0.0f, d1y = 0.0f, d1z = 0.0f;
        int base1 = -1;
        if (nexti < ntiles)
            base1 = prep_tile(x, d, M, nexti, tid, sbase[nbuf], d1x, d1y, d1z);

        __syncthreads();   // sbase[nbuf] ready; prior compute's srec[nbuf] reads done

        if (nexti < ntiles)
            gather_tile(vg, sbase[nbuf], srec[nbuf], tid);
        asm volatile("cp.async.commit_group;\n" ::: "memory");   // possibly empty group

        asm volatile("cp.async.wait_group 1;\n" ::: "memory");   // tile i's copies done
        __syncthreads();                                         // ...across all threads

        // COMPUTE tile i
        {
            int ray = i * TILE + tid;
            if (ray < M) {
                float* color = out + 3 * (size_t)ray;
                float* sigma = out + 3 * (size_t)M + ray;
                if (base0 >= 0) {
                    const float4* t4 = (const float4*)&srec[buf][tid * 28];
                    float4 v0 = t4[0];
                    float4 v1 = t4[1];
                    float4 v2 = t4[2];
                    float4 v3 = t4[3];
                    float4 v4 = t4[4];
                    float4 v5 = t4[5];
                    float4 v6 = t4[6];
                    float t[28] = {
                        v0.x, v0.y, v0.z, v0.w,  v1.x, v1.y, v1.z, v1.w,
                        v2.x, v2.y, v2.z, v2.w,  v3.x, v3.y, v3.z, v3.w,
                        v4.x, v4.y, v4.z, v4.w,  v5.x, v5.y, v5.z, v5.w,
                        v6.x, v6.y, v6.z, v6.w,
                    };

                    *sigma = fmaxf(t[0], 0.0f);

                    float b0 = 0.282095f;
                    float b1 = -0.488603f * d0y;
                    float b2 = 0.488603f * d0z;
                    float b3 = -0.488603f * d0x;
                    float b4 = 1.092548f * d0x * d0y;
                    float b5 = -1.092548f * d0y * d0z;
                    float b6 = 0.315392f * (2.0f * d0z * d0z - d0x * d0x - d0y * d0y);
                    float b7 = -1.092548f * d0x * d0z;
                    float b8 = 0.546274f * (d0x * d0x - d0y * d0y);

                    #pragma unroll
                    for (int c = 0; c < 3; c++) {
                        const float* k = t + 1 + 9 * c;
                        float acc;
                        acc = b0 * k[0];
                        acc = fmaf(b1, k[1], acc);
                        acc = fmaf(b2, k[2], acc);
                        acc = fmaf(b3, k[3], acc);
                        acc = fmaf(b4, k[4], acc);
                        acc = fmaf(b5, k[5], acc);
                        acc = fmaf(b6, k[6], acc);
                        acc = fmaf(b7, k[7], acc);
                        acc = fmaf(b8, k[8], acc);
                        color[c] = acc;
                    }
                } else {
                    color[0] = 0.0f;
                    color[1] = 0.0f;
                    color[2] = 0.0f;
                    *sigma = 0.0f;
                }
            }
        }

        i = nexti;
        buf = nbuf;
        base0 = base1;
        d0x = d1x; d0y = d1y; d0z = d1z;
    }
}

extern "C" void kernel_launch(void* const* d_in, const int* in_sizes, int n_in,
                              void* d_out, int out_size) {
    const float* x  = (const float*)d_in[0];
    const float* d  = (const float*)d_in[1];
    const float* vg = (const float*)d_in[2];
    float* out = (float*)d_out;

    int M = in_sizes[0] / 3;
    int ntiles = (M + TILE - 1) / TILE;

    // ~7 blocks/SM (29.7 KB smem each) on 148 SMs, persistent grid-stride.
    int grid = 148 * 7;
    if (grid > ntiles) grid = ntiles;
    nerf_kernel<<<grid, BLK>>>(x, d, vg, out, M, ntiles);
}